// round 3
// baseline (speedup 1.0000x reference)
#include <cuda_runtime.h>

#define N_USERS 100000
#define N_ITEMS 50000
#define N_NODES (N_USERS + N_ITEMS)
#define N_EDGES 4800000
#define EMB 64
#define TOTAL (N_NODES * EMB)

// Scratch (allocation-free): ping-pong embedding buffers, 38.4 MB each.
// Referenced directly by symbol inside kernels — no cudaGetSymbolAddress.
__device__ float g_bufA[TOTAL];
__device__ float g_bufB[TOTAL];

// ---------------------------------------------------------------------------
// init: bufA = concat(user, item); out = bufA (acc term for layer 0); bufB = 0
// ---------------------------------------------------------------------------
__global__ void k_init(const float* __restrict__ user_emb,
                       const float* __restrict__ item_emb,
                       float* __restrict__ out) {
    int i = blockIdx.x * blockDim.x + threadIdx.x;
    if (i >= TOTAL) return;
    float v = (i < N_USERS * EMB) ? user_emb[i] : item_emb[i - N_USERS * EMB];
    g_bufA[i] = v;
    g_bufB[i] = 0.0f;
    out[i]    = v;
}

// ---------------------------------------------------------------------------
// SpMM: y[rows[e]] += vals[e] * x[cols[e]]   (scatter-add, L2-resident table)
// 16 threads per edge, each thread owns one float4 chunk of the 64-dim row.
// red.global.add.v4.f32 = no-return vector reduction -> 4x fewer L2 atomic ops.
// DIR=0: A -> B, DIR=1: B -> A (buffers picked at compile time per launch).
// ---------------------------------------------------------------------------
template <int DIR>
__global__ void k_spmm(const int*   __restrict__ rows,
                       const int*   __restrict__ cols,
                       const float* __restrict__ vals) {
    unsigned int t = blockIdx.x * blockDim.x + threadIdx.x;
    unsigned int e = t >> 4;          // edge index
    if (e >= N_EDGES) return;
    int chunk = t & 15;               // which float4 of the 64-dim row

    const float* __restrict__ x = (DIR == 0) ? g_bufA : g_bufB;
    float*       __restrict__ y = (DIR == 0) ? g_bufB : g_bufA;

    int   r = __ldg(rows + e);
    int   c = __ldg(cols + e);
    float v = __ldg(vals + e);

    const float4* src = reinterpret_cast<const float4*>(x + (size_t)c * EMB);
    float4 xv = __ldg(src + chunk);

    float4 m;
    m.x = xv.x * v; m.y = xv.y * v; m.z = xv.z * v; m.w = xv.w * v;

    float* dst = y + (size_t)r * EMB + chunk * 4;
    asm volatile("red.global.add.v4.f32 [%0], {%1, %2, %3, %4};"
                 :: "l"(dst), "f"(m.x), "f"(m.y), "f"(m.z), "f"(m.w)
                 : "memory");
}

// ---------------------------------------------------------------------------
// acc += layer_result;  zero the other buffer (next scatter target)
// DIR=0: out += B, zero A.   DIR=1: out += A, zero B.
// ---------------------------------------------------------------------------
template <int DIR>
__global__ void k_accum_zero(float* __restrict__ out) {
    int i = blockIdx.x * blockDim.x + threadIdx.x;
    if (i >= TOTAL) return;
    const float* added  = (DIR == 0) ? g_bufB : g_bufA;
    float*       zeroed = (DIR == 0) ? g_bufA : g_bufB;
    out[i] += added[i];
    zeroed[i] = 0.0f;
}

// ---------------------------------------------------------------------------
// final: out = (out + g_bufB) / 4
// ---------------------------------------------------------------------------
__global__ void k_final(float* __restrict__ out) {
    int i = blockIdx.x * blockDim.x + threadIdx.x;
    if (i >= TOTAL) return;
    out[i] = (out[i] + g_bufB[i]) * 0.25f;
}

extern "C" void kernel_launch(void* const* d_in, const int* in_sizes, int n_in,
                              void* d_out, int out_size) {
    const int*   adj_rows = (const int*)  d_in[0];
    const int*   adj_cols = (const int*)  d_in[1];
    const float* adj_vals = (const float*)d_in[2];
    const float* user_emb = (const float*)d_in[3];
    const float* item_emb = (const float*)d_in[4];
    float* out = (float*)d_out;

    const int ELEM_BLK = 256;
    const int elem_grid = (TOTAL + ELEM_BLK - 1) / ELEM_BLK;

    const int SPMM_BLK = 256;
    const long long spmm_threads = (long long)N_EDGES * 16;
    const int spmm_grid = (int)((spmm_threads + SPMM_BLK - 1) / SPMM_BLK);

    // emb0 into A, acc (=out) = emb0, B zeroed as scatter target
    k_init<<<elem_grid, ELEM_BLK>>>(user_emb, item_emb, out);

    // layer 1: A -> B
    k_spmm<0><<<spmm_grid, SPMM_BLK>>>(adj_rows, adj_cols, adj_vals);
    k_accum_zero<0><<<elem_grid, ELEM_BLK>>>(out);   // acc += B; A = 0

    // layer 2: B -> A
    k_spmm<1><<<spmm_grid, SPMM_BLK>>>(adj_rows, adj_cols, adj_vals);
    k_accum_zero<1><<<elem_grid, ELEM_BLK>>>(out);   // acc += A; B = 0

    // layer 3: A -> B, then out = (acc + B) / 4
    k_spmm<0><<<spmm_grid, SPMM_BLK>>>(adj_rows, adj_cols, adj_vals);
    k_final<<<elem_grid, ELEM_BLK>>>(out);
}

// round 5
// speedup vs baseline: 1.9594x; 1.9594x over previous
#include <cuda_runtime.h>

#define N_USERS 100000
#define N_ITEMS 50000
#define N_NODES (N_USERS + N_ITEMS)
#define N_EDGES 4800000
#define EMB 64
#define TOTAL (N_NODES * EMB)

#define SCAN_CHUNK 1024                      // elements per scan block
#define NBLK_SCAN ((N_NODES + SCAN_CHUNK - 1) / SCAN_CHUNK)   // 147

// ---- device scratch (allocation-free) -------------------------------------
__device__ float g_bufA[TOTAL];              // ping-pong embeddings (38.4 MB)
__device__ float g_bufB[TOTAL];
__device__ int2  g_ew[N_EDGES];              // CSR payload: (col, val-bits) 38.4 MB
__device__ int   g_counts[N_NODES];
__device__ int   g_offs[N_NODES + 1];
__device__ int   g_cursor[N_NODES];
__device__ int   g_part[NBLK_SCAN];

// ---------------------------------------------------------------------------
// init: bufA = concat(user,item); out = bufA (layer-0 acc term); counts = 0
// ---------------------------------------------------------------------------
__global__ void k_init(const float* __restrict__ user_emb,
                       const float* __restrict__ item_emb,
                       float* __restrict__ out) {
    int i = blockIdx.x * blockDim.x + threadIdx.x;
    if (i < N_NODES) g_counts[i] = 0;
    if (i >= TOTAL) return;
    float v = (i < N_USERS * EMB) ? user_emb[i] : item_emb[i - N_USERS * EMB];
    g_bufA[i] = v;
    out[i]    = v;
}

// ---------------------------------------------------------------------------
// CSR build step 1: per-row degree histogram
// ---------------------------------------------------------------------------
__global__ void k_count(const int* __restrict__ rows) {
    int e = blockIdx.x * blockDim.x + threadIdx.x;
    if (e >= N_EDGES) return;
    atomicAdd(&g_counts[__ldg(rows + e)], 1);
}

// CSR build step 2a: per-chunk sums
__global__ void k_scan1() {
    __shared__ int sm[256];
    int t = threadIdx.x;
    int idx = blockIdx.x * SCAN_CHUNK + t * 4;
    int s = 0;
#pragma unroll
    for (int k = 0; k < 4; k++) { int i = idx + k; if (i < N_NODES) s += g_counts[i]; }
    sm[t] = s; __syncthreads();
    for (int st = 128; st > 0; st >>= 1) { if (t < st) sm[t] += sm[t + st]; __syncthreads(); }
    if (t == 0) g_part[blockIdx.x] = sm[0];
}

// CSR build step 2b: exclusive scan of chunk sums (single block)
__global__ void k_scan2() {
    __shared__ int sm[256];
    int t = threadIdx.x;
    int v = (t < NBLK_SCAN) ? g_part[t] : 0;
    sm[t] = v; __syncthreads();
    for (int s = 1; s < 256; s <<= 1) {
        int u = (t >= s) ? sm[t - s] : 0;
        __syncthreads();
        sm[t] += u;
        __syncthreads();
    }
    if (t < NBLK_SCAN) g_part[t] = sm[t] - v;     // exclusive
    if (t == 0) g_offs[N_NODES] = N_EDGES;        // every edge has a valid row
}

// CSR build step 2c: intra-chunk exclusive scan -> offsets & cursor
__global__ void k_scan3() {
    __shared__ int sm[256];
    int t = threadIdx.x;
    int idx = blockIdx.x * SCAN_CHUNK + t * 4;
    int c[4];
#pragma unroll
    for (int k = 0; k < 4; k++) c[k] = (idx + k < N_NODES) ? g_counts[idx + k] : 0;
    int tsum = c[0] + c[1] + c[2] + c[3];
    sm[t] = tsum; __syncthreads();
    for (int s = 1; s < 256; s <<= 1) {
        int u = (t >= s) ? sm[t - s] : 0;
        __syncthreads();
        sm[t] += u;
        __syncthreads();
    }
    int p = g_part[blockIdx.x] + sm[t] - tsum;    // exclusive prefix for this thread
#pragma unroll
    for (int k = 0; k < 4; k++) {
        int i = idx + k;
        if (i < N_NODES) { g_offs[i] = p; g_cursor[i] = p; }
        p += c[k];
    }
}

// CSR build step 3: scatter edges into row-grouped payload
__global__ void k_scatter(const int*   __restrict__ rows,
                          const int*   __restrict__ cols,
                          const float* __restrict__ vals) {
    int e = blockIdx.x * blockDim.x + threadIdx.x;
    if (e >= N_EDGES) return;
    int r = __ldg(rows + e);
    int pos = atomicAdd(&g_cursor[r], 1);
    g_ew[pos] = make_int2(__ldg(cols + e), __float_as_int(__ldg(vals + e)));
}

// ---------------------------------------------------------------------------
// Gather SpMM layer: one warp per row; lane l owns features [2l, 2l+1].
// Edge meta read coalesced 32/warp, broadcast via shfl. No atomics.
// Fused: y[row]=sum; acc(out) += sum  (or final: out=(out+sum)*0.25).
// DIR=0: x=A -> y=B.  DIR=1: x=B -> y=A.
// ---------------------------------------------------------------------------
template <int DIR, bool FINAL>
__global__ void k_gather(float* __restrict__ out) {
    int warp_id = (blockIdx.x * blockDim.x + threadIdx.x) >> 5;
    if (warp_id >= N_NODES) return;
    int lane = threadIdx.x & 31;

    const float* __restrict__ x = (DIR == 0) ? g_bufA : g_bufB;
    float*       __restrict__ y = (DIR == 0) ? g_bufB : g_bufA;

    int start = g_offs[warp_id];
    int end   = g_offs[warp_id + 1];

    float ax = 0.f, ay = 0.f;
    int base = start;

    // full 32-edge tiles
    for (; base + 32 <= end; base += 32) {
        int2 ev = g_ew[base + lane];
        int   c = ev.x;
        float v = __int_as_float(ev.y);
#pragma unroll 8
        for (int j = 0; j < 32; ++j) {
            int   cj = __shfl_sync(0xffffffffu, c, j);
            float vj = __shfl_sync(0xffffffffu, v, j);
            float2 xv = *reinterpret_cast<const float2*>(x + ((size_t)cj << 6) + (lane << 1));
            ax = fmaf(vj, xv.x, ax);
            ay = fmaf(vj, xv.y, ay);
        }
    }
    // remainder
    int rem = end - base;
    if (rem > 0) {
        int c = 0; float v = 0.f;
        if (lane < rem) {
            int2 ev = g_ew[base + lane];
            c = ev.x; v = __int_as_float(ev.y);
        }
        for (int j = 0; j < rem; ++j) {
            int   cj = __shfl_sync(0xffffffffu, c, j);
            float vj = __shfl_sync(0xffffffffu, v, j);
            float2 xv = *reinterpret_cast<const float2*>(x + ((size_t)cj << 6) + (lane << 1));
            ax = fmaf(vj, xv.x, ax);
            ay = fmaf(vj, xv.y, ay);
        }
    }

    size_t oi = ((size_t)warp_id << 6) + (lane << 1);
    float2* op = reinterpret_cast<float2*>(out + oi);
    float2 o = *op;
    if (FINAL) {
        o.x = (o.x + ax) * 0.25f;
        o.y = (o.y + ay) * 0.25f;
        *op = o;
    } else {
        o.x += ax; o.y += ay;
        *op = o;
        *reinterpret_cast<float2*>(y + oi) = make_float2(ax, ay);
    }
}

extern "C" void kernel_launch(void* const* d_in, const int* in_sizes, int n_in,
                              void* d_out, int out_size) {
    const int*   adj_rows = (const int*)  d_in[0];
    const int*   adj_cols = (const int*)  d_in[1];
    const float* adj_vals = (const float*)d_in[2];
    const float* user_emb = (const float*)d_in[3];
    const float* item_emb = (const float*)d_in[4];
    float* out = (float*)d_out;

    const int BLK = 256;
    const int elem_grid   = (TOTAL + BLK - 1) / BLK;
    const int edge_grid   = (N_EDGES + BLK - 1) / BLK;
    const int gather_grid = ((N_NODES * 32) + BLK - 1) / BLK;

    // init embeddings + acc, zero degree counters
    k_init<<<elem_grid, BLK>>>(user_emb, item_emb, out);

    // CSR build (paid once, used by 3 layers)
    k_count  <<<edge_grid, BLK>>>(adj_rows);
    k_scan1  <<<NBLK_SCAN, 256>>>();
    k_scan2  <<<1, 256>>>();
    k_scan3  <<<NBLK_SCAN, 256>>>();
    k_scatter<<<edge_grid, BLK>>>(adj_rows, adj_cols, adj_vals);

    // 3 propagation layers, atomic-free, acc fused
    k_gather<0, false><<<gather_grid, BLK>>>(out);   // A -> B, out += B
    k_gather<1, false><<<gather_grid, BLK>>>(out);   // B -> A, out += A
    k_gather<0, true ><<<gather_grid, BLK>>>(out);   // A -> B, out = (out+B)/4
}

// round 8
// speedup vs baseline: 2.7509x; 1.4040x over previous
#include <cuda_runtime.h>
#include <cuda_fp16.h>

#define N_USERS 100000
#define N_ITEMS 50000
#define N_NODES (N_USERS + N_ITEMS)
#define N_EDGES 4800000
#define EMB 64
#define TOTAL (N_NODES * EMB)
#define UELEMS (N_USERS * EMB)

#define SCAN_CHUNK 1024
#define NBLK_SCAN ((N_NODES + SCAN_CHUNK - 1) / SCAN_CHUNK)   // 147

// ---- device scratch (allocation-free) -------------------------------------
__device__ __half g_H0[TOTAL];          // layer-0 embeddings (fp16 copy), 19.2MB
__device__ __half g_H1[TOTAL];          // layer-1 output
__device__ __half g_H2[TOTAL];          // layer-2 output
__device__ __half g_H3[TOTAL];          // layer-3 output
__device__ int2   g_ew[N_EDGES];        // CSR payload: (col, val-bits), 38.4MB
__device__ int    g_counts[N_NODES];
__device__ int    g_offs[N_NODES + 1];
__device__ int    g_cursor[N_NODES];
__device__ int    g_part[NBLK_SCAN];

// ---------------------------------------------------------------------------
// init: H0 = half(concat(user,item)); counts = 0
// ---------------------------------------------------------------------------
__global__ void k_init(const float* __restrict__ user_emb,
                       const float* __restrict__ item_emb) {
    int i = blockIdx.x * blockDim.x + threadIdx.x;
    if (i < N_NODES) g_counts[i] = 0;
    if (i >= TOTAL) return;
    float v = (i < UELEMS) ? user_emb[i] : item_emb[i - UELEMS];
    g_H0[i] = __float2half_rn(v);
}

// CSR build step 1: per-row degree histogram
__global__ void k_count(const int* __restrict__ rows) {
    int e = blockIdx.x * blockDim.x + threadIdx.x;
    if (e >= N_EDGES) return;
    atomicAdd(&g_counts[__ldg(rows + e)], 1);
}

// CSR build step 2a: per-chunk sums
__global__ void k_scan1() {
    __shared__ int sm[256];
    int t = threadIdx.x;
    int idx = blockIdx.x * SCAN_CHUNK + t * 4;
    int s = 0;
#pragma unroll
    for (int k = 0; k < 4; k++) { int i = idx + k; if (i < N_NODES) s += g_counts[i]; }
    sm[t] = s; __syncthreads();
    for (int st = 128; st > 0; st >>= 1) { if (t < st) sm[t] += sm[t + st]; __syncthreads(); }
    if (t == 0) g_part[blockIdx.x] = sm[0];
}

// CSR build step 2b: exclusive scan of chunk sums (single block)
__global__ void k_scan2() {
    __shared__ int sm[256];
    int t = threadIdx.x;
    int v = (t < NBLK_SCAN) ? g_part[t] : 0;
    sm[t] = v; __syncthreads();
    for (int s = 1; s < 256; s <<= 1) {
        int u = (t >= s) ? sm[t - s] : 0;
        __syncthreads();
        sm[t] += u;
        __syncthreads();
    }
    if (t < NBLK_SCAN) g_part[t] = sm[t] - v;     // exclusive
    if (t == 0) g_offs[N_NODES] = N_EDGES;
}

// CSR build step 2c: intra-chunk exclusive scan -> offsets & cursor
__global__ void k_scan3() {
    __shared__ int sm[256];
    int t = threadIdx.x;
    int idx = blockIdx.x * SCAN_CHUNK + t * 4;
    int c[4];
#pragma unroll
    for (int k = 0; k < 4; k++) c[k] = (idx + k < N_NODES) ? g_counts[idx + k] : 0;
    int tsum = c[0] + c[1] + c[2] + c[3];
    sm[t] = tsum; __syncthreads();
    for (int s = 1; s < 256; s <<= 1) {
        int u = (t >= s) ? sm[t - s] : 0;
        __syncthreads();
        sm[t] += u;
        __syncthreads();
    }
    int p = g_part[blockIdx.x] + sm[t] - tsum;
#pragma unroll
    for (int k = 0; k < 4; k++) {
        int i = idx + k;
        if (i < N_NODES) { g_offs[i] = p; g_cursor[i] = p; }
        p += c[k];
    }
}

// CSR build step 3: scatter edges into row-grouped payload
__global__ void k_scatter(const int*   __restrict__ rows,
                          const int*   __restrict__ cols,
                          const float* __restrict__ vals) {
    int e = blockIdx.x * blockDim.x + threadIdx.x;
    if (e >= N_EDGES) return;
    int r = __ldg(rows + e);
    int pos = atomicAdd(&g_cursor[r], 1);
    g_ew[pos] = make_int2(__ldg(cols + e), __float_as_int(__ldg(vals + e)));
}

// ---------------------------------------------------------------------------
// Gather SpMM layer (fp16 storage, fp32 accumulation, no atomics).
// 16 lanes per row, 2 rows per warp. Lane owns 4 features (8B load).
// Edge meta coalesced 16/half-warp, broadcast via width-16 shfl with
// per-half masks (halves may diverge on different degrees).
// ---------------------------------------------------------------------------
__global__ void k_gather(const __half* __restrict__ x,
                         __half*       __restrict__ y) {
    int gw = (blockIdx.x * blockDim.x + threadIdx.x) >> 5;   // warp id
    int lane = threadIdx.x & 31;
    int half_id = lane >> 4;
    int hl = lane & 15;
    int r = gw * 2 + half_id;
    if (r >= N_NODES) return;                                 // N_NODES even: full warps
    unsigned mask = 0xFFFFu << (half_id * 16);

    int start = g_offs[r];
    int end   = g_offs[r + 1];

    float a0 = 0.f, a1 = 0.f, a2 = 0.f, a3 = 0.f;
    int base = start;

    for (; base + 16 <= end; base += 16) {
        int2 ev = g_ew[base + hl];
        int   c = ev.x;
        float v = __int_as_float(ev.y);
#pragma unroll 4
        for (int j = 0; j < 16; ++j) {
            int   cj = __shfl_sync(mask, c, j, 16);
            float vj = __shfl_sync(mask, v, j, 16);
            uint2 raw = *reinterpret_cast<const uint2*>(x + ((size_t)cj << 6) + (hl << 2));
            float2 f0 = __half22float2(*reinterpret_cast<__half2*>(&raw.x));
            float2 f1 = __half22float2(*reinterpret_cast<__half2*>(&raw.y));
            a0 = fmaf(vj, f0.x, a0);
            a1 = fmaf(vj, f0.y, a1);
            a2 = fmaf(vj, f1.x, a2);
            a3 = fmaf(vj, f1.y, a3);
        }
    }
    int rem = end - base;
    if (rem > 0) {
        int c = 0; float v = 0.f;
        if (hl < rem) {
            int2 ev = g_ew[base + hl];
            c = ev.x; v = __int_as_float(ev.y);
        }
        for (int j = 0; j < rem; ++j) {
            int   cj = __shfl_sync(mask, c, j, 16);
            float vj = __shfl_sync(mask, v, j, 16);
            uint2 raw = *reinterpret_cast<const uint2*>(x + ((size_t)cj << 6) + (hl << 2));
            float2 f0 = __half22float2(*reinterpret_cast<__half2*>(&raw.x));
            float2 f1 = __half22float2(*reinterpret_cast<__half2*>(&raw.y));
            a0 = fmaf(vj, f0.x, a0);
            a1 = fmaf(vj, f0.y, a1);
            a2 = fmaf(vj, f1.x, a2);
            a3 = fmaf(vj, f1.y, a3);
        }
    }

    __half2 o0 = __floats2half2_rn(a0, a1);
    __half2 o1 = __floats2half2_rn(a2, a3);
    uint2 packed;
    packed.x = *reinterpret_cast<unsigned int*>(&o0);
    packed.y = *reinterpret_cast<unsigned int*>(&o1);
    *reinterpret_cast<uint2*>(y + ((size_t)r << 6) + (hl << 2)) = packed;
}

// ---------------------------------------------------------------------------
// final: out = 0.25 * (fp32 inputs + H1 + H2 + H3), 4 floats / thread
// ---------------------------------------------------------------------------
__global__ void k_final(const float* __restrict__ user_emb,
                        const float* __restrict__ item_emb,
                        float* __restrict__ out) {
    int t = blockIdx.x * blockDim.x + threadIdx.x;
    size_t i4 = (size_t)t * 4;
    if (i4 >= TOTAL) return;

    float4 b = (i4 < UELEMS)
        ? *reinterpret_cast<const float4*>(user_emb + i4)
        : *reinterpret_cast<const float4*>(item_emb + (i4 - UELEMS));

    uint2 r1 = *reinterpret_cast<const uint2*>(g_H1 + i4);
    uint2 r2 = *reinterpret_cast<const uint2*>(g_H2 + i4);
    uint2 r3 = *reinterpret_cast<const uint2*>(g_H3 + i4);

    float2 e1a = __half22float2(*reinterpret_cast<__half2*>(&r1.x));
    float2 e1b = __half22float2(*reinterpret_cast<__half2*>(&r1.y));
    float2 e2a = __half22float2(*reinterpret_cast<__half2*>(&r2.x));
    float2 e2b = __half22float2(*reinterpret_cast<__half2*>(&r2.y));
    float2 e3a = __half22float2(*reinterpret_cast<__half2*>(&r3.x));
    float2 e3b = __half22float2(*reinterpret_cast<__half2*>(&r3.y));

    float4 o;
    o.x = (b.x + e1a.x + e2a.x + e3a.x) * 0.25f;
    o.y = (b.y + e1a.y + e2a.y + e3a.y) * 0.25f;
    o.z = (b.z + e1b.x + e2b.x + e3b.x) * 0.25f;
    o.w = (b.w + e1b.y + e2b.y + e3b.y) * 0.25f;
    *reinterpret_cast<float4*>(out + i4) = o;
}

extern "C" void kernel_launch(void* const* d_in, const int* in_sizes, int n_in,
                              void* d_out, int out_size) {
    const int*   adj_rows = (const int*)  d_in[0];
    const int*   adj_cols = (const int*)  d_in[1];
    const float* adj_vals = (const float*)d_in[2];
    const float* user_emb = (const float*)d_in[3];
    const float* item_emb = (const float*)d_in[4];
    float* out = (float*)d_out;

    __half* H0; cudaGetSymbolAddress((void**)&H0, g_H0);
    __half* H1; cudaGetSymbolAddress((void**)&H1, g_H1);
    __half* H2; cudaGetSymbolAddress((void**)&H2, g_H2);
    __half* H3; cudaGetSymbolAddress((void**)&H3, g_H3);

    const int BLK = 256;
    const int elem_grid   = (TOTAL + BLK - 1) / BLK;
    const int edge_grid   = (N_EDGES + BLK - 1) / BLK;
    const int gather_grid = ((N_NODES / 2) * 32 + BLK - 1) / BLK;   // 2 rows/warp
    const int final_grid  = (TOTAL / 4 + BLK - 1) / BLK;

    k_init<<<elem_grid, BLK>>>(user_emb, item_emb);

    // CSR build (paid once, used by 3 layers)
    k_count  <<<edge_grid, BLK>>>(adj_rows);
    k_scan1  <<<NBLK_SCAN, 256>>>();
    k_scan2  <<<1, 256>>>();
    k_scan3  <<<NBLK_SCAN, 256>>>();
    k_scatter<<<edge_grid, BLK>>>(adj_rows, adj_cols, adj_vals);

    // 3 atomic-free propagation layers, fp16 storage / fp32 accumulation
    k_gather<<<gather_grid, BLK>>>(H0, H1);
    k_gather<<<gather_grid, BLK>>>(H1, H2);
    k_gather<<<gather_grid, BLK>>>(H2, H3);

    k_final<<<final_grid, BLK>>>(user_emb, item_emb, out);
}